// round 2
// baseline (speedup 1.0000x reference)
#include <cuda_runtime.h>

typedef unsigned long long u64;

// Packed f32x2 subtract (Blackwell; valid). There is NO packed f32 min on sm_103a.
__device__ __forceinline__ u64 sub2(u64 a, u64 b) {
    u64 d; asm("sub.rn.f32x2 %0, %1, %2;" : "=l"(d) : "l"(a), "l"(b)); return d;
}
__device__ __forceinline__ void unpk(u64 v, float& lo, float& hi) {
    asm("mov.b64 {%0, %1}, %2;" : "=f"(lo), "=f"(hi) : "l"(v));
}

constexpr int B = 1024, F = 784, D = 512;
constexpr int TB = 64, TD = 64, TF = 56;   // 784 = 14 * 56
constexpr int SX = 60;                      // padded smem row stride (floats)
constexpr int NSTEP = F / TF;               // 14

__global__ __launch_bounds__(256, 1)
void dendral_kernel(const float* __restrict__ x,
                    const float* __restrict__ wmin,
                    const float* __restrict__ wmax,
                    float* __restrict__ out)
{
    __shared__ float sx [TB * SX];
    __shared__ float smn[TD * SX];
    __shared__ float smx[TD * SX];

    const int tid = threadIdx.x;
    const int tx  = tid & 15;    // d lane
    const int ty  = tid >> 4;    // b lane
    const int d0  = blockIdx.x * TD;
    const int b0  = blockIdx.y * TB;

    const float INF = __int_as_float(0x7F800000);
    float2 acc[4][4];
    #pragma unroll
    for (int i = 0; i < 4; ++i)
        #pragma unroll
        for (int j = 0; j < 4; ++j) acc[i][j] = make_float2(INF, INF);

    for (int k = 0; k < NSTEP; ++k) {
        const int f0 = k * TF;
        __syncthreads();  // protect smem reuse from previous step

        // Load tiles: 64 rows x 14 float4 = 896 float4 per array.
        #pragma unroll
        for (int t = 0; t < 4; ++t) {
            int idx = tid + t * 256;
            if (idx < 896) {
                int row = idx / 14;
                int c4  = idx % 14;
                float4 vx = *(const float4*)&x   [(b0 + row) * F + f0 + c4 * 4];
                float4 vn = *(const float4*)&wmin[(d0 + row) * F + f0 + c4 * 4];
                float4 vm = *(const float4*)&wmax[(d0 + row) * F + f0 + c4 * 4];
                *(float4*)&sx [row * SX + c4 * 4] = vx;
                *(float4*)&smn[row * SX + c4 * 4] = vn;
                *(float4*)&smx[row * SX + c4 * 4] = vm;
            }
        }
        __syncthreads();

        #pragma unroll 2
        for (int f = 0; f < TF; f += 4) {
            ulonglong2 xv[4], nv[4], mv[4];
            #pragma unroll
            for (int j = 0; j < 4; ++j)
                xv[j] = *(const ulonglong2*)&sx[(ty + 16 * j) * SX + f];
            #pragma unroll
            for (int i = 0; i < 4; ++i) {
                nv[i] = *(const ulonglong2*)&smn[(tx + 16 * i) * SX + f];
                mv[i] = *(const ulonglong2*)&smx[(tx + 16 * i) * SX + f];
            }
            #pragma unroll
            for (int i = 0; i < 4; ++i)
                #pragma unroll
                for (int j = 0; j < 4; ++j) {
                    // f pair 0/1
                    u64 t1a = sub2(xv[j].x, nv[i].x);   // x - Wmin
                    u64 t2a = sub2(mv[i].x, xv[j].x);   // Wmax - x
                    // f pair 2/3
                    u64 t1b = sub2(xv[j].y, nv[i].y);
                    u64 t2b = sub2(mv[i].y, xv[j].y);

                    float a0, a1, b0_, b1_, c0, c1, d0_, d1_;
                    unpk(t1a, a0, a1);
                    unpk(t2a, b0_, b1_);
                    unpk(t1b, c0, c1);
                    unpk(t2b, d0_, d1_);

                    // cross-min the independent streams first (no acc dependence),
                    // then one acc-min per lane per f-pair: short dependency chain.
                    float m0 = fminf(a0, b0_);
                    float m1 = fminf(a1, b1_);
                    float m2 = fminf(c0, d0_);
                    float m3 = fminf(c1, d1_);
                    acc[i][j].x = fminf(acc[i][j].x, m0);
                    acc[i][j].y = fminf(acc[i][j].y, m1);
                    acc[i][j].x = fminf(acc[i][j].x, m2);
                    acc[i][j].y = fminf(acc[i][j].y, m3);
                }
        }
    }

    // Epilogue: horizontal min of the two f-lanes, coalesced store.
    #pragma unroll
    for (int i = 0; i < 4; ++i)
        #pragma unroll
        for (int j = 0; j < 4; ++j) {
            int b = b0 + ty + 16 * j;
            int d = d0 + tx + 16 * i;
            out[b * D + d] = fminf(acc[i][j].x, acc[i][j].y);
        }
}

extern "C" void kernel_launch(void* const* d_in, const int* in_sizes, int n_in,
                              void* d_out, int out_size)
{
    const float* x    = (const float*)d_in[0];
    const float* wmin = (const float*)d_in[1];
    const float* wmax = (const float*)d_in[2];
    float* out = (float*)d_out;

    dim3 grid(D / TD, B / TB);   // (8, 16) = 128 CTAs
    dendral_kernel<<<grid, 256>>>(x, wmin, wmax, out);
}